// round 10
// baseline (speedup 1.0000x reference)
#include <cuda_runtime.h>
#include <cstdint>

#define BB 16
#define CC 256
#define HWD 1024
// H = W = 32, K_conv = 9*256 = 2304

// Scratch (allocation-free: device globals)
__device__ float g_fn [2][BB][CC][HWD];    // normalized features (tf32-rounded)
__device__ float g_val[2][BB][CC][HWD];    // conv-projected values (tf32-rounded)
__device__ float g_aff[2][BB][HWD][HWD];   // cosine affinity
__device__ float g_M  [BB][HWD][HWD];      // fused attention map (tf32-rounded)
__device__ float g_wT [2][2304][CC];       // transposed proj weights [k=d*256+ci][co]

// ---------------------------------------------------------------------------
__device__ __forceinline__ float tf32r(float x) {
    uint32_t u;
    asm("cvt.rna.tf32.f32 %0, %1;" : "=r"(u) : "f"(x));
    return __uint_as_float(u);
}

__device__ __forceinline__ void mma8(float* c, const float* a, const float* b) {
    const uint32_t* A = reinterpret_cast<const uint32_t*>(a);
    const uint32_t* B = reinterpret_cast<const uint32_t*>(b);
    asm volatile(
        "mma.sync.aligned.m16n8k8.row.col.f32.tf32.tf32.f32 "
        "{%0,%1,%2,%3}, {%4,%5,%6,%7}, {%8,%9}, {%0,%1,%2,%3};"
        : "+f"(c[0]), "+f"(c[1]), "+f"(c[2]), "+f"(c[3])
        : "r"(A[0]), "r"(A[1]), "r"(A[2]), "r"(A[3]), "r"(B[0]), "r"(B[1]));
}

// ---------------------------------------------------------------------------
// K1: column-wise L2 normalize over C for each (b, s); output tf32-rounded.
// ---------------------------------------------------------------------------
__global__ void k_normalize(const float* __restrict__ f0,
                            const float* __restrict__ f1) {
    int t = blockIdx.z;
    int b = blockIdx.y;
    int s = blockIdx.x * 256 + threadIdx.x;
    const float* f = (t == 0 ? f0 : f1) + (size_t)b * CC * HWD;
    float ss = 0.f;
#pragma unroll 8
    for (int c = 0; c < CC; c++) {
        float v = f[c * HWD + s];
        ss += v * v;
    }
    float inv = 1.0f / fmaxf(sqrtf(ss), 1e-12f);
    float* fn = &g_fn[t][b][0][0];
#pragma unroll 8
    for (int c = 0; c < CC; c++)
        fn[c * HWD + s] = tf32r(f[c * HWD + s] * inv);
}

// ---------------------------------------------------------------------------
// K1b: transpose + tf32-round proj weights: g_wT[t][d*256+ci][co]
// ---------------------------------------------------------------------------
__global__ void k_wprep(const float* __restrict__ w0,
                        const float* __restrict__ w1) {
    int co = blockIdx.x;
    int t  = blockIdx.y;
    const float* w = (t == 0 ? w0 : w1) + (size_t)co * 2304;
    for (int i = threadIdx.x; i < 2304; i += 256) {
        int ci = i / 9, d = i - ci * 9;
        g_wT[t][d * 256 + ci][co] = tf32r(w[i]);
    }
}

// ---------------------------------------------------------------------------
// K2: proj conv as implicit GEMM (tf32 mma).
// M=256 couts, N=1024 px, K=2304 (d-major: k = d*256 + ci).
// Block 128x128, 8 warps as 4(M)x2(N), warp tile 32x64.
// ---------------------------------------------------------------------------
__global__ void __launch_bounds__(256, 2)
k_conv_mma(const float* __restrict__ f0, const float* __restrict__ f1,
           const float* __restrict__ bias0, const float* __restrict__ bias1) {
    int t  = blockIdx.z;
    int b  = blockIdx.y;
    int bm = blockIdx.x & 1;
    int bn = blockIdx.x >> 1;
    const float* f    = (t == 0 ? f0 : f1) + (size_t)b * CC * HWD;
    const float* bias = (t == 0 ? bias0 : bias1);
    const float* wT   = &g_wT[t][0][0];

    __shared__ float sA[16][132];
    __shared__ float sB[16][132];

    int tid = threadIdx.x, lane = tid & 31, warp = tid >> 5;
    int wm = (warp >> 1) * 32, wn = (warp & 1) * 64;
    int r = lane >> 2, kq = lane & 3;
    int m0 = bm * 128, n0 = bn * 128;

    float acc[2][8][4];
#pragma unroll
    for (int mm = 0; mm < 2; mm++)
#pragma unroll
        for (int nn = 0; nn < 8; nn++)
#pragma unroll
            for (int i = 0; i < 4; i++) acc[mm][nn][i] = 0.f;

    int akk = tid >> 4, acol = (tid & 15) * 8;

    for (int c = 0; c < 144; c++) {
        int d = c >> 4, ci0 = (c & 15) << 4;
        int dy = d / 3 - 1, dx = d % 3 - 1;
        // A tile: weights, coalesced float4 (already tf32)
        {
            const float* src = wT + (size_t)(d * 256 + ci0 + akk) * 256 + m0 + acol;
            *(float4*)&sA[akk][acol]     = *(const float4*)src;
            *(float4*)&sA[akk][acol + 4] = *(const float4*)(src + 4);
        }
        // B tile: shifted feature gather with zero pad, tf32-round
#pragma unroll
        for (int q = 0; q < 8; q++) {
            int idx = tid + 256 * q;
            int kk = idx >> 7, n = idx & 127;
            int p = n0 + n;
            int ys = (p >> 5) + dy, xs = (p & 31) + dx;
            float v = 0.f;
            if ((unsigned)ys < 32u && (unsigned)xs < 32u)
                v = f[(ci0 + kk) * HWD + (ys << 5) + xs];
            sB[kk][n] = tf32r(v);
        }
        __syncthreads();
#pragma unroll
        for (int ks = 0; ks < 16; ks += 8) {
            float afr[2][4], bfr[8][2];
#pragma unroll
            for (int mm = 0; mm < 2; mm++) {
                afr[mm][0] = sA[ks + kq][wm + mm * 16 + r];
                afr[mm][1] = sA[ks + kq][wm + mm * 16 + r + 8];
                afr[mm][2] = sA[ks + kq + 4][wm + mm * 16 + r];
                afr[mm][3] = sA[ks + kq + 4][wm + mm * 16 + r + 8];
            }
#pragma unroll
            for (int nn = 0; nn < 8; nn++) {
                bfr[nn][0] = sB[ks + kq][wn + nn * 8 + r];
                bfr[nn][1] = sB[ks + kq + 4][wn + nn * 8 + r];
            }
#pragma unroll
            for (int mm = 0; mm < 2; mm++)
#pragma unroll
                for (int nn = 0; nn < 8; nn++)
                    mma8(acc[mm][nn], afr[mm], bfr[nn]);
        }
        __syncthreads();
    }

    float* out = &g_val[t][b][0][0];
#pragma unroll
    for (int mm = 0; mm < 2; mm++)
#pragma unroll
        for (int half = 0; half < 2; half++) {
            int row = m0 + wm + mm * 16 + r + half * 8;
            float bb = bias[row];
#pragma unroll
            for (int nn = 0; nn < 8; nn++) {
                int col = n0 + wn + nn * 8 + 2 * kq;
                float v0 = tf32r(acc[mm][nn][half * 2 + 0] + bb);
                float v1 = tf32r(acc[mm][nn][half * 2 + 1] + bb);
                *(float2*)&out[(size_t)row * HWD + col] = make_float2(v0, v1);
            }
        }
}

// ---------------------------------------------------------------------------
// K3: aff = fn^T fn (tf32 mma), symmetric: 36 of 64 128x128 block pairs.
// ---------------------------------------------------------------------------
__global__ void __launch_bounds__(256, 2)
k_aff_mma() {
    int t = blockIdx.z, b = blockIdx.y;
    int p = blockIdx.x;
    int bi = 0;
    while (p >= 8 - bi) { p -= 8 - bi; bi++; }
    int bj = bi + p;

    const float* fn = &g_fn[t][b][0][0];   // [C][HW], K-major
    __shared__ float sA[16][132];
    __shared__ float sB[16][132];

    int tid = threadIdx.x, lane = tid & 31, warp = tid >> 5;
    int wm = (warp >> 1) * 32, wn = (warp & 1) * 64;
    int r = lane >> 2, kq = lane & 3;
    int i0 = bi * 128, j0 = bj * 128;

    float acc[2][8][4];
#pragma unroll
    for (int mm = 0; mm < 2; mm++)
#pragma unroll
        for (int nn = 0; nn < 8; nn++)
#pragma unroll
            for (int i = 0; i < 4; i++) acc[mm][nn][i] = 0.f;

    int akk = tid >> 4, acol = (tid & 15) * 8;

    for (int c = 0; c < 16; c++) {
        int k0 = c * 16;
        const float* sa = &fn[(size_t)(k0 + akk) * HWD + i0 + acol];
        const float* sb = &fn[(size_t)(k0 + akk) * HWD + j0 + acol];
        *(float4*)&sA[akk][acol]     = *(const float4*)sa;
        *(float4*)&sA[akk][acol + 4] = *(const float4*)(sa + 4);
        *(float4*)&sB[akk][acol]     = *(const float4*)sb;
        *(float4*)&sB[akk][acol + 4] = *(const float4*)(sb + 4);
        __syncthreads();
#pragma unroll
        for (int ks = 0; ks < 16; ks += 8) {
            float afr[2][4], bfr[8][2];
#pragma unroll
            for (int mm = 0; mm < 2; mm++) {
                afr[mm][0] = sA[ks + kq][wm + mm * 16 + r];
                afr[mm][1] = sA[ks + kq][wm + mm * 16 + r + 8];
                afr[mm][2] = sA[ks + kq + 4][wm + mm * 16 + r];
                afr[mm][3] = sA[ks + kq + 4][wm + mm * 16 + r + 8];
            }
#pragma unroll
            for (int nn = 0; nn < 8; nn++) {
                bfr[nn][0] = sB[ks + kq][wn + nn * 8 + r];
                bfr[nn][1] = sB[ks + kq + 4][wn + nn * 8 + r];
            }
#pragma unroll
            for (int mm = 0; mm < 2; mm++)
#pragma unroll
                for (int nn = 0; nn < 8; nn++)
                    mma8(acc[mm][nn], afr[mm], bfr[nn]);
        }
        __syncthreads();
    }

    float* aff = &g_aff[t][b][0][0];
#pragma unroll
    for (int mm = 0; mm < 2; mm++)
#pragma unroll
        for (int half = 0; half < 2; half++) {
            int gi = i0 + wm + mm * 16 + r + half * 8;
#pragma unroll
            for (int nn = 0; nn < 8; nn++) {
                int gj = j0 + wn + nn * 8 + 2 * kq;
                float v0 = acc[mm][nn][half * 2 + 0];
                float v1 = acc[mm][nn][half * 2 + 1];
                *(float2*)&aff[(size_t)gi * HWD + gj] = make_float2(v0, v1);
                if (bi != bj) {
                    aff[(size_t)gj * HWD + gi]       = v0;
                    aff[(size_t)(gj + 1) * HWD + gi] = v1;
                }
            }
        }
}

// ---------------------------------------------------------------------------
// K4: grouped fusion conv (fp32), output tf32-rounded for the attend GEMM.
// ---------------------------------------------------------------------------
__global__ void k_fusion(const float* __restrict__ fw,
                         const float* __restrict__ fb) {
    int j = blockIdx.x, b = blockIdx.y;
    __shared__ float t0[34 * 34];
    __shared__ float t1[34 * 34];
    __shared__ float wsh[18];
    int tid = threadIdx.x;
    const float* a0 = &g_aff[0][b][j][0];
    const float* a1 = &g_aff[1][b][j][0];
    for (int idx = tid; idx < 34 * 34; idx += 256) {
        int y = idx / 34, x = idx - y * 34;
        int gy = y - 1, gx = x - 1;
        bool in = (unsigned)gy < 32u && (unsigned)gx < 32u;
        t0[idx] = in ? a0[gy * 32 + gx] : 0.f;
        t1[idx] = in ? a1[gy * 32 + gx] : 0.f;
    }
    if (tid < 18) wsh[tid] = fw[j * 18 + tid];
    __syncthreads();
    float bb = fb[j];
    float* out = &g_M[b][j][0];
#pragma unroll
    for (int q = 0; q < 4; q++) {
        int p = tid + 256 * q;
        int y = p >> 5, x = p & 31;
        float s = bb;
#pragma unroll
        for (int dy = 0; dy < 3; dy++)
#pragma unroll
            for (int dx = 0; dx < 3; dx++) {
                int ti = (y + dy) * 34 + (x + dx);
                s += t0[ti] * wsh[dy * 3 + dx];
                s += t1[ti] * wsh[9 + dy * 3 + dx];
            }
        out[p] = tf32r(s);
    }
}

// ---------------------------------------------------------------------------
// K5: attended[c][j] = sum_k val[c][k]*M[j][k]  (tf32 mma NT GEMM),
// fused epilogue out = 0.5*acc + 0.5*f straight to d_out.
// ---------------------------------------------------------------------------
__global__ void __launch_bounds__(256, 2)
k_attend_mma(const float* __restrict__ f0, const float* __restrict__ f1,
             float* __restrict__ out) {
    int t  = blockIdx.z;
    int b  = blockIdx.y;
    int bm = blockIdx.x & 1;
    int bn = blockIdx.x >> 1;
    const float* V  = &g_val[t][b][0][0];  // [256][1024], k contiguous
    const float* Mm = &g_M[b][0][0];       // [1024][1024], k contiguous

    __shared__ float sA[16][132];
    __shared__ float sB[16][132];

    int tid = threadIdx.x, lane = tid & 31, warp = tid >> 5;
    int wm = (warp >> 1) * 32, wn = (warp & 1) * 64;
    int r = lane >> 2, kq = lane & 3;
    int m0 = bm * 128, n0 = bn * 128;

    float acc[2][8][4];
#pragma unroll
    for (int mm = 0; mm < 2; mm++)
#pragma unroll
        for (int nn = 0; nn < 8; nn++)
#pragma unroll
            for (int i = 0; i < 4; i++) acc[mm][nn][i] = 0.f;

    int lrow = tid >> 1;          // 0..127
    int kh   = (tid & 1) * 8;     // 0 or 8

    for (int c = 0; c < 64; c++) {
        int k0 = c * 16;
        {
            const float* pa = &V[(size_t)(m0 + lrow) * HWD + k0 + kh];
            float4 v0 = *(const float4*)pa;
            float4 v1 = *(const float4*)(pa + 4);
            sA[kh + 0][lrow] = v0.x; sA[kh + 1][lrow] = v0.y;
            sA[kh + 2][lrow] = v0.z; sA[kh + 3][lrow] = v0.w;
            sA[kh + 4][lrow] = v1.x; sA[kh + 5][lrow] = v1.y;
            sA[kh + 6][lrow] = v1.z; sA[kh + 7][lrow] = v1.w;
            const float* pb = &Mm[(size_t)(n0 + lrow) * HWD + k0 + kh];
            float4 w0 = *(const float4*)pb;
            float4 w1 = *(const float4*)(pb + 4);
            sB[kh + 0][lrow] = w0.x; sB[kh + 1][lrow] = w0.y;
            sB[kh + 2][lrow] = w0.z; sB[kh + 3][lrow] = w0.w;
            sB[kh + 4][lrow] = w1.x; sB[kh + 5][lrow] = w1.y;
            sB[kh + 6][lrow] = w1.z; sB[kh + 7][lrow] = w1.w;
        }
        __syncthreads();
#pragma unroll
        for (int ks = 0; ks < 16; ks += 8) {
            float afr[2][4], bfr[8][2];
#pragma unroll
            for (int mm = 0; mm < 2; mm++) {
                afr[mm][0] = sA[ks + kq][wm + mm * 16 + r];
                afr[mm][1] = sA[ks + kq][wm + mm * 16 + r + 8];
                afr[mm][2] = sA[ks + kq + 4][wm + mm * 16 + r];
                afr[mm][3] = sA[ks + kq + 4][wm + mm * 16 + r + 8];
            }
#pragma unroll
            for (int nn = 0; nn < 8; nn++) {
                bfr[nn][0] = sB[ks + kq][wn + nn * 8 + r];
                bfr[nn][1] = sB[ks + kq + 4][wn + nn * 8 + r];
            }
#pragma unroll
            for (int mm = 0; mm < 2; mm++)
#pragma unroll
                for (int nn = 0; nn < 8; nn++)
                    mma8(acc[mm][nn], afr[mm], bfr[nn]);
        }
        __syncthreads();
    }

    const float* f = (t == 0 ? f0 : f1) + (size_t)b * CC * HWD;
    float* o = out + ((size_t)t * BB + b) * CC * HWD;
#pragma unroll
    for (int mm = 0; mm < 2; mm++)
#pragma unroll
        for (int half = 0; half < 2; half++) {
            int row = m0 + wm + mm * 16 + r + half * 8;
#pragma unroll
            for (int nn = 0; nn < 8; nn++) {
                int col = n0 + wn + nn * 8 + 2 * kq;
                float2 fv = *(const float2*)&f[(size_t)row * HWD + col];
                float v0 = 0.5f * acc[mm][nn][half * 2 + 0] + 0.5f * fv.x;
                float v1 = 0.5f * acc[mm][nn][half * 2 + 1] + 0.5f * fv.y;
                *(float2*)&o[(size_t)row * HWD + col] = make_float2(v0, v1);
            }
        }
}

// ---------------------------------------------------------------------------
extern "C" void kernel_launch(void* const* d_in, const int* in_sizes, int n_in,
                              void* d_out, int out_size) {
    const float* f0 = (const float*)d_in[0];   // features_seg
    const float* f1 = (const float*)d_in[1];   // features_depth
    const float* w0 = (const float*)d_in[2];   // proj_w_seg
    const float* b0 = (const float*)d_in[3];   // proj_b_seg
    const float* w1 = (const float*)d_in[4];   // proj_w_depth
    const float* b1 = (const float*)d_in[5];   // proj_b_depth
    const float* fw = (const float*)d_in[6];   // fusion_w
    const float* fb = (const float*)d_in[7];   // fusion_b
    float* out = (float*)d_out;

    k_normalize<<<dim3(4, 16, 2), 256>>>(f0, f1);
    k_wprep<<<dim3(256, 2), 256>>>(w0, w1);
    k_conv_mma<<<dim3(16, 16, 2), 256>>>(f0, f1, b0, b1);
    k_aff_mma<<<dim3(36, 16, 2), 256>>>();
    k_fusion<<<dim3(1024, 16), 256>>>(fw, fb);
    k_attend_mma<<<dim3(16, 16, 2), 256>>>(f0, f1, out);
}

// round 11
// speedup vs baseline: 1.0007x; 1.0007x over previous
#include <cuda_runtime.h>
#include <cstdint>

#define BB 16
#define CC 256
#define HWD 1024
// H = W = 32, K_conv = 9*256 = 2304

// Scratch (allocation-free: device globals)
__device__ float g_fn [2][BB][CC][HWD];    // normalized features (tf32-rounded)
__device__ float g_val[2][BB][CC][HWD];    // conv-projected values (tf32-rounded)
__device__ float g_aff[2][BB][HWD][HWD];   // cosine affinity
__device__ float g_M  [BB][HWD][HWD];      // fused attention map (tf32-rounded)
__device__ float g_wT [2][2304][CC];       // transposed proj weights [k=d*256+ci][co]

// ---------------------------------------------------------------------------
__device__ __forceinline__ float tf32r(float x) {
    uint32_t u;
    asm("cvt.rna.tf32.f32 %0, %1;" : "=r"(u) : "f"(x));
    return __uint_as_float(u);
}

__device__ __forceinline__ void mma8(float* c, const float* a, const float* b) {
    const uint32_t* A = reinterpret_cast<const uint32_t*>(a);
    const uint32_t* B = reinterpret_cast<const uint32_t*>(b);
    asm volatile(
        "mma.sync.aligned.m16n8k8.row.col.f32.tf32.tf32.f32 "
        "{%0,%1,%2,%3}, {%4,%5,%6,%7}, {%8,%9}, {%0,%1,%2,%3};"
        : "+f"(c[0]), "+f"(c[1]), "+f"(c[2]), "+f"(c[3])
        : "r"(A[0]), "r"(A[1]), "r"(A[2]), "r"(A[3]), "r"(B[0]), "r"(B[1]));
}

// ---------------------------------------------------------------------------
// K1: column-wise L2 normalize over C for each (b, s); output tf32-rounded.
// ---------------------------------------------------------------------------
__global__ void k_normalize(const float* __restrict__ f0,
                            const float* __restrict__ f1) {
    int t = blockIdx.z;
    int b = blockIdx.y;
    int s = blockIdx.x * 256 + threadIdx.x;
    const float* f = (t == 0 ? f0 : f1) + (size_t)b * CC * HWD;
    float ss = 0.f;
#pragma unroll 8
    for (int c = 0; c < CC; c++) {
        float v = f[c * HWD + s];
        ss += v * v;
    }
    float inv = 1.0f / fmaxf(sqrtf(ss), 1e-12f);
    float* fn = &g_fn[t][b][0][0];
#pragma unroll 8
    for (int c = 0; c < CC; c++)
        fn[c * HWD + s] = tf32r(f[c * HWD + s] * inv);
}

// ---------------------------------------------------------------------------
// K1b: transpose + tf32-round proj weights: g_wT[t][d*256+ci][co]
// ---------------------------------------------------------------------------
__global__ void k_wprep(const float* __restrict__ w0,
                        const float* __restrict__ w1) {
    int co = blockIdx.x;
    int t  = blockIdx.y;
    const float* w = (t == 0 ? w0 : w1) + (size_t)co * 2304;
    for (int i = threadIdx.x; i < 2304; i += 256) {
        int ci = i / 9, d = i - ci * 9;
        g_wT[t][d * 256 + ci][co] = tf32r(w[i]);
    }
}

// ---------------------------------------------------------------------------
// K2: proj conv as implicit GEMM (tf32 mma).
// M=256 couts, N=1024 px, K=2304 (d-major: k = d*256 + ci).
// Block 128x128, 8 warps as 4(M)x2(N), warp tile 32x64.
// ---------------------------------------------------------------------------
__global__ void __launch_bounds__(256, 2)
k_conv_mma(const float* __restrict__ f0, const float* __restrict__ f1,
           const float* __restrict__ bias0, const float* __restrict__ bias1) {
    int t  = blockIdx.z;
    int b  = blockIdx.y;
    int bm = blockIdx.x & 1;
    int bn = blockIdx.x >> 1;
    const float* f    = (t == 0 ? f0 : f1) + (size_t)b * CC * HWD;
    const float* bias = (t == 0 ? bias0 : bias1);
    const float* wT   = &g_wT[t][0][0];

    __shared__ float sA[16][132];
    __shared__ float sB[16][132];

    int tid = threadIdx.x, lane = tid & 31, warp = tid >> 5;
    int wm = (warp >> 1) * 32, wn = (warp & 1) * 64;
    int r = lane >> 2, kq = lane & 3;
    int m0 = bm * 128, n0 = bn * 128;

    float acc[2][8][4];
#pragma unroll
    for (int mm = 0; mm < 2; mm++)
#pragma unroll
        for (int nn = 0; nn < 8; nn++)
#pragma unroll
            for (int i = 0; i < 4; i++) acc[mm][nn][i] = 0.f;

    int akk = tid >> 4, acol = (tid & 15) * 8;

    for (int c = 0; c < 144; c++) {
        int d = c >> 4, ci0 = (c & 15) << 4;
        int dy = d / 3 - 1, dx = d % 3 - 1;
        // A tile: weights, coalesced float4 (already tf32)
        {
            const float* src = wT + (size_t)(d * 256 + ci0 + akk) * 256 + m0 + acol;
            *(float4*)&sA[akk][acol]     = *(const float4*)src;
            *(float4*)&sA[akk][acol + 4] = *(const float4*)(src + 4);
        }
        // B tile: shifted feature gather with zero pad, tf32-round
#pragma unroll
        for (int q = 0; q < 8; q++) {
            int idx = tid + 256 * q;
            int kk = idx >> 7, n = idx & 127;
            int p = n0 + n;
            int ys = (p >> 5) + dy, xs = (p & 31) + dx;
            float v = 0.f;
            if ((unsigned)ys < 32u && (unsigned)xs < 32u)
                v = f[(ci0 + kk) * HWD + (ys << 5) + xs];
            sB[kk][n] = tf32r(v);
        }
        __syncthreads();
#pragma unroll
        for (int ks = 0; ks < 16; ks += 8) {
            float afr[2][4], bfr[8][2];
#pragma unroll
            for (int mm = 0; mm < 2; mm++) {
                afr[mm][0] = sA[ks + kq][wm + mm * 16 + r];
                afr[mm][1] = sA[ks + kq][wm + mm * 16 + r + 8];
                afr[mm][2] = sA[ks + kq + 4][wm + mm * 16 + r];
                afr[mm][3] = sA[ks + kq + 4][wm + mm * 16 + r + 8];
            }
#pragma unroll
            for (int nn = 0; nn < 8; nn++) {
                bfr[nn][0] = sB[ks + kq][wn + nn * 8 + r];
                bfr[nn][1] = sB[ks + kq + 4][wn + nn * 8 + r];
            }
#pragma unroll
            for (int mm = 0; mm < 2; mm++)
#pragma unroll
                for (int nn = 0; nn < 8; nn++)
                    mma8(acc[mm][nn], afr[mm], bfr[nn]);
        }
        __syncthreads();
    }

    float* out = &g_val[t][b][0][0];
#pragma unroll
    for (int mm = 0; mm < 2; mm++)
#pragma unroll
        for (int half = 0; half < 2; half++) {
            int row = m0 + wm + mm * 16 + r + half * 8;
            float bb = bias[row];
#pragma unroll
            for (int nn = 0; nn < 8; nn++) {
                int col = n0 + wn + nn * 8 + 2 * kq;
                float v0 = tf32r(acc[mm][nn][half * 2 + 0] + bb);
                float v1 = tf32r(acc[mm][nn][half * 2 + 1] + bb);
                *(float2*)&out[(size_t)row * HWD + col] = make_float2(v0, v1);
            }
        }
}

// ---------------------------------------------------------------------------
// K3: aff = fn^T fn (tf32 mma), symmetric: 36 of 64 128x128 block pairs.
// ---------------------------------------------------------------------------
__global__ void __launch_bounds__(256, 2)
k_aff_mma() {
    int t = blockIdx.z, b = blockIdx.y;
    int p = blockIdx.x;
    int bi = 0;
    while (p >= 8 - bi) { p -= 8 - bi; bi++; }
    int bj = bi + p;

    const float* fn = &g_fn[t][b][0][0];   // [C][HW], K-major
    __shared__ float sA[16][132];
    __shared__ float sB[16][132];

    int tid = threadIdx.x, lane = tid & 31, warp = tid >> 5;
    int wm = (warp >> 1) * 32, wn = (warp & 1) * 64;
    int r = lane >> 2, kq = lane & 3;
    int i0 = bi * 128, j0 = bj * 128;

    float acc[2][8][4];
#pragma unroll
    for (int mm = 0; mm < 2; mm++)
#pragma unroll
        for (int nn = 0; nn < 8; nn++)
#pragma unroll
            for (int i = 0; i < 4; i++) acc[mm][nn][i] = 0.f;

    int akk = tid >> 4, acol = (tid & 15) * 8;

    for (int c = 0; c < 16; c++) {
        int k0 = c * 16;
        const float* sa = &fn[(size_t)(k0 + akk) * HWD + i0 + acol];
        const float* sb = &fn[(size_t)(k0 + akk) * HWD + j0 + acol];
        *(float4*)&sA[akk][acol]     = *(const float4*)sa;
        *(float4*)&sA[akk][acol + 4] = *(const float4*)(sa + 4);
        *(float4*)&sB[akk][acol]     = *(const float4*)sb;
        *(float4*)&sB[akk][acol + 4] = *(const float4*)(sb + 4);
        __syncthreads();
#pragma unroll
        for (int ks = 0; ks < 16; ks += 8) {
            float afr[2][4], bfr[8][2];
#pragma unroll
            for (int mm = 0; mm < 2; mm++) {
                afr[mm][0] = sA[ks + kq][wm + mm * 16 + r];
                afr[mm][1] = sA[ks + kq][wm + mm * 16 + r + 8];
                afr[mm][2] = sA[ks + kq + 4][wm + mm * 16 + r];
                afr[mm][3] = sA[ks + kq + 4][wm + mm * 16 + r + 8];
            }
#pragma unroll
            for (int nn = 0; nn < 8; nn++) {
                bfr[nn][0] = sB[ks + kq][wn + nn * 8 + r];
                bfr[nn][1] = sB[ks + kq + 4][wn + nn * 8 + r];
            }
#pragma unroll
            for (int mm = 0; mm < 2; mm++)
#pragma unroll
                for (int nn = 0; nn < 8; nn++)
                    mma8(acc[mm][nn], afr[mm], bfr[nn]);
        }
        __syncthreads();
    }

    float* aff = &g_aff[t][b][0][0];
#pragma unroll
    for (int mm = 0; mm < 2; mm++)
#pragma unroll
        for (int half = 0; half < 2; half++) {
            int gi = i0 + wm + mm * 16 + r + half * 8;
#pragma unroll
            for (int nn = 0; nn < 8; nn++) {
                int gj = j0 + wn + nn * 8 + 2 * kq;
                float v0 = acc[mm][nn][half * 2 + 0];
                float v1 = acc[mm][nn][half * 2 + 1];
                *(float2*)&aff[(size_t)gi * HWD + gj] = make_float2(v0, v1);
                if (bi != bj) {
                    aff[(size_t)gj * HWD + gi]       = v0;
                    aff[(size_t)(gj + 1) * HWD + gi] = v1;
                }
            }
        }
}

// ---------------------------------------------------------------------------
// K4: grouped fusion conv (fp32), output tf32-rounded for the attend GEMM.
// ---------------------------------------------------------------------------
__global__ void k_fusion(const float* __restrict__ fw,
                         const float* __restrict__ fb) {
    int j = blockIdx.x, b = blockIdx.y;
    __shared__ float t0[34 * 34];
    __shared__ float t1[34 * 34];
    __shared__ float wsh[18];
    int tid = threadIdx.x;
    const float* a0 = &g_aff[0][b][j][0];
    const float* a1 = &g_aff[1][b][j][0];
    for (int idx = tid; idx < 34 * 34; idx += 256) {
        int y = idx / 34, x = idx - y * 34;
        int gy = y - 1, gx = x - 1;
        bool in = (unsigned)gy < 32u && (unsigned)gx < 32u;
        t0[idx] = in ? a0[gy * 32 + gx] : 0.f;
        t1[idx] = in ? a1[gy * 32 + gx] : 0.f;
    }
    if (tid < 18) wsh[tid] = fw[j * 18 + tid];
    __syncthreads();
    float bb = fb[j];
    float* out = &g_M[b][j][0];
#pragma unroll
    for (int q = 0; q < 4; q++) {
        int p = tid + 256 * q;
        int y = p >> 5, x = p & 31;
        float s = bb;
#pragma unroll
        for (int dy = 0; dy < 3; dy++)
#pragma unroll
            for (int dx = 0; dx < 3; dx++) {
                int ti = (y + dy) * 34 + (x + dx);
                s += t0[ti] * wsh[dy * 3 + dx];
                s += t1[ti] * wsh[9 + dy * 3 + dx];
            }
        out[p] = tf32r(s);
    }
}

// ---------------------------------------------------------------------------
// K5: attended[c][j] = sum_k val[c][k]*M[j][k]  (tf32 mma NT GEMM),
// fused epilogue out = 0.5*acc + 0.5*f straight to d_out.
// ---------------------------------------------------------------------------
__global__ void __launch_bounds__(256, 2)
k_attend_mma(const float* __restrict__ f0, const float* __restrict__ f1,
             float* __restrict__ out) {
    int t  = blockIdx.z;
    int b  = blockIdx.y;
    int bm = blockIdx.x & 1;
    int bn = blockIdx.x >> 1;
    const float* V  = &g_val[t][b][0][0];  // [256][1024], k contiguous
    const float* Mm = &g_M[b][0][0];       // [1024][1024], k contiguous

    __shared__ float sA[16][132];
    __shared__ float sB[16][132];

    int tid = threadIdx.x, lane = tid & 31, warp = tid >> 5;
    int wm = (warp >> 1) * 32, wn = (warp & 1) * 64;
    int r = lane >> 2, kq = lane & 3;
    int m0 = bm * 128, n0 = bn * 128;

    float acc[2][8][4];
#pragma unroll
    for (int mm = 0; mm < 2; mm++)
#pragma unroll
        for (int nn = 0; nn < 8; nn++)
#pragma unroll
            for (int i = 0; i < 4; i++) acc[mm][nn][i] = 0.f;

    int lrow = tid >> 1;          // 0..127
    int kh   = (tid & 1) * 8;     // 0 or 8

    for (int c = 0; c < 64; c++) {
        int k0 = c * 16;
        {
            const float* pa = &V[(size_t)(m0 + lrow) * HWD + k0 + kh];
            float4 v0 = *(const float4*)pa;
            float4 v1 = *(const float4*)(pa + 4);
            sA[kh + 0][lrow] = v0.x; sA[kh + 1][lrow] = v0.y;
            sA[kh + 2][lrow] = v0.z; sA[kh + 3][lrow] = v0.w;
            sA[kh + 4][lrow] = v1.x; sA[kh + 5][lrow] = v1.y;
            sA[kh + 6][lrow] = v1.z; sA[kh + 7][lrow] = v1.w;
            const float* pb = &Mm[(size_t)(n0 + lrow) * HWD + k0 + kh];
            float4 w0 = *(const float4*)pb;
            float4 w1 = *(const float4*)(pb + 4);
            sB[kh + 0][lrow] = w0.x; sB[kh + 1][lrow] = w0.y;
            sB[kh + 2][lrow] = w0.z; sB[kh + 3][lrow] = w0.w;
            sB[kh + 4][lrow] = w1.x; sB[kh + 5][lrow] = w1.y;
            sB[kh + 6][lrow] = w1.z; sB[kh + 7][lrow] = w1.w;
        }
        __syncthreads();
#pragma unroll
        for (int ks = 0; ks < 16; ks += 8) {
            float afr[2][4], bfr[8][2];
#pragma unroll
            for (int mm = 0; mm < 2; mm++) {
                afr[mm][0] = sA[ks + kq][wm + mm * 16 + r];
                afr[mm][1] = sA[ks + kq][wm + mm * 16 + r + 8];
                afr[mm][2] = sA[ks + kq + 4][wm + mm * 16 + r];
                afr[mm][3] = sA[ks + kq + 4][wm + mm * 16 + r + 8];
            }
#pragma unroll
            for (int nn = 0; nn < 8; nn++) {
                bfr[nn][0] = sB[ks + kq][wn + nn * 8 + r];
                bfr[nn][1] = sB[ks + kq + 4][wn + nn * 8 + r];
            }
#pragma unroll
            for (int mm = 0; mm < 2; mm++)
#pragma unroll
                for (int nn = 0; nn < 8; nn++)
                    mma8(acc[mm][nn], afr[mm], bfr[nn]);
        }
        __syncthreads();
    }

    const float* f = (t == 0 ? f0 : f1) + (size_t)b * CC * HWD;
    float* o = out + ((size_t)t * BB + b) * CC * HWD;
#pragma unroll
    for (int mm = 0; mm < 2; mm++)
#pragma unroll
        for (int half = 0; half < 2; half++) {
            int row = m0 + wm + mm * 16 + r + half * 8;
#pragma unroll
            for (int nn = 0; nn < 8; nn++) {
                int col = n0 + wn + nn * 8 + 2 * kq;
                float2 fv = *(const float2*)&f[(size_t)row * HWD + col];
                float v0 = 0.5f * acc[mm][nn][half * 2 + 0] + 0.5f * fv.x;
                float v1 = 0.5f * acc[mm][nn][half * 2 + 1] + 0.5f * fv.y;
                *(float2*)&o[(size_t)row * HWD + col] = make_float2(v0, v1);
            }
        }
}

// ---------------------------------------------------------------------------
extern "C" void kernel_launch(void* const* d_in, const int* in_sizes, int n_in,
                              void* d_out, int out_size) {
    const float* f0 = (const float*)d_in[0];   // features_seg
    const float* f1 = (const float*)d_in[1];   // features_depth
    const float* w0 = (const float*)d_in[2];   // proj_w_seg
    const float* b0 = (const float*)d_in[3];   // proj_b_seg
    const float* w1 = (const float*)d_in[4];   // proj_w_depth
    const float* b1 = (const float*)d_in[5];   // proj_b_depth
    const float* fw = (const float*)d_in[6];   // fusion_w
    const float* fb = (const float*)d_in[7];   // fusion_b
    float* out = (float*)d_out;

    k_normalize<<<dim3(4, 16, 2), 256>>>(f0, f1);
    k_wprep<<<dim3(256, 2), 256>>>(w0, w1);
    k_conv_mma<<<dim3(16, 16, 2), 256>>>(f0, f1, b0, b1);
    k_aff_mma<<<dim3(36, 16, 2), 256>>>();
    k_fusion<<<dim3(1024, 16), 256>>>(fw, fb);
    k_attend_mma<<<dim3(16, 16, 2), 256>>>(f0, f1, out);
}

// round 12
// speedup vs baseline: 1.0028x; 1.0021x over previous
#include <cuda_runtime.h>
#include <cstdint>

#define BB 16
#define CC 256
#define HWD 1024
// H = W = 32, K_conv = 9*256 = 2304

// Scratch (allocation-free: device globals)
__device__ float g_fn [2][BB][CC][HWD];    // normalized features (tf32-rounded)
__device__ float g_val[2][BB][CC][HWD];    // conv-projected values (tf32-rounded)
__device__ float g_aff[2][BB][HWD][HWD];   // cosine affinity
__device__ float g_M  [BB][HWD][HWD];      // fused attention map (tf32-rounded)
__device__ float g_wT [2][2304][CC];       // transposed proj weights [k=d*256+ci][co]

// ---------------------------------------------------------------------------
__device__ __forceinline__ float tf32r(float x) {
    uint32_t u;
    asm("cvt.rna.tf32.f32 %0, %1;" : "=r"(u) : "f"(x));
    return __uint_as_float(u);
}

__device__ __forceinline__ void mma8(float* c, const float* a, const float* b) {
    const uint32_t* A = reinterpret_cast<const uint32_t*>(a);
    const uint32_t* B = reinterpret_cast<const uint32_t*>(b);
    asm volatile(
        "mma.sync.aligned.m16n8k8.row.col.f32.tf32.tf32.f32 "
        "{%0,%1,%2,%3}, {%4,%5,%6,%7}, {%8,%9}, {%0,%1,%2,%3};"
        : "+f"(c[0]), "+f"(c[1]), "+f"(c[2]), "+f"(c[3])
        : "r"(A[0]), "r"(A[1]), "r"(A[2]), "r"(A[3]), "r"(B[0]), "r"(B[1]));
}

// ---------------------------------------------------------------------------
// K1: column-wise L2 normalize over C for each (b, s); output tf32-rounded.
// ---------------------------------------------------------------------------
__global__ void k_normalize(const float* __restrict__ f0,
                            const float* __restrict__ f1) {
    int t = blockIdx.z;
    int b = blockIdx.y;
    int s = blockIdx.x * 256 + threadIdx.x;
    const float* f = (t == 0 ? f0 : f1) + (size_t)b * CC * HWD;
    float ss = 0.f;
#pragma unroll 8
    for (int c = 0; c < CC; c++) {
        float v = f[c * HWD + s];
        ss += v * v;
    }
    float inv = 1.0f / fmaxf(sqrtf(ss), 1e-12f);
    float* fn = &g_fn[t][b][0][0];
#pragma unroll 8
    for (int c = 0; c < CC; c++)
        fn[c * HWD + s] = tf32r(f[c * HWD + s] * inv);
}

// ---------------------------------------------------------------------------
// K1b: transpose + tf32-round proj weights: g_wT[t][d*256+ci][co]
// ---------------------------------------------------------------------------
__global__ void k_wprep(const float* __restrict__ w0,
                        const float* __restrict__ w1) {
    int co = blockIdx.x;
    int t  = blockIdx.y;
    const float* w = (t == 0 ? w0 : w1) + (size_t)co * 2304;
    for (int i = threadIdx.x; i < 2304; i += 256) {
        int ci = i / 9, d = i - ci * 9;
        g_wT[t][d * 256 + ci][co] = tf32r(w[i]);
    }
}

// ---------------------------------------------------------------------------
// K2: proj conv as implicit GEMM (tf32 mma).
// M=256 couts, N=1024 px, K=2304 (d-major: k = d*256 + ci).
// Block 128x128, 8 warps as 4(M)x2(N), warp tile 32x64.
// ---------------------------------------------------------------------------
__global__ void __launch_bounds__(256, 2)
k_conv_mma(const float* __restrict__ f0, const float* __restrict__ f1,
           const float* __restrict__ bias0, const float* __restrict__ bias1) {
    int t  = blockIdx.z;
    int b  = blockIdx.y;
    int bm = blockIdx.x & 1;
    int bn = blockIdx.x >> 1;
    const float* f    = (t == 0 ? f0 : f1) + (size_t)b * CC * HWD;
    const float* bias = (t == 0 ? bias0 : bias1);
    const float* wT   = &g_wT[t][0][0];

    __shared__ float sA[16][132];
    __shared__ float sB[16][132];

    int tid = threadIdx.x, lane = tid & 31, warp = tid >> 5;
    int wm = (warp >> 1) * 32, wn = (warp & 1) * 64;
    int r = lane >> 2, kq = lane & 3;
    int m0 = bm * 128, n0 = bn * 128;

    float acc[2][8][4];
#pragma unroll
    for (int mm = 0; mm < 2; mm++)
#pragma unroll
        for (int nn = 0; nn < 8; nn++)
#pragma unroll
            for (int i = 0; i < 4; i++) acc[mm][nn][i] = 0.f;

    int akk = tid >> 4, acol = (tid & 15) * 8;

    for (int c = 0; c < 144; c++) {
        int d = c >> 4, ci0 = (c & 15) << 4;
        int dy = d / 3 - 1, dx = d % 3 - 1;
        // A tile: weights, coalesced float4 (already tf32)
        {
            const float* src = wT + (size_t)(d * 256 + ci0 + akk) * 256 + m0 + acol;
            *(float4*)&sA[akk][acol]     = *(const float4*)src;
            *(float4*)&sA[akk][acol + 4] = *(const float4*)(src + 4);
        }
        // B tile: shifted feature gather with zero pad, tf32-round
#pragma unroll
        for (int q = 0; q < 8; q++) {
            int idx = tid + 256 * q;
            int kk = idx >> 7, n = idx & 127;
            int p = n0 + n;
            int ys = (p >> 5) + dy, xs = (p & 31) + dx;
            float v = 0.f;
            if ((unsigned)ys < 32u && (unsigned)xs < 32u)
                v = f[(ci0 + kk) * HWD + (ys << 5) + xs];
            sB[kk][n] = tf32r(v);
        }
        __syncthreads();
#pragma unroll
        for (int ks = 0; ks < 16; ks += 8) {
            float afr[2][4], bfr[8][2];
#pragma unroll
            for (int mm = 0; mm < 2; mm++) {
                afr[mm][0] = sA[ks + kq][wm + mm * 16 + r];
                afr[mm][1] = sA[ks + kq][wm + mm * 16 + r + 8];
                afr[mm][2] = sA[ks + kq + 4][wm + mm * 16 + r];
                afr[mm][3] = sA[ks + kq + 4][wm + mm * 16 + r + 8];
            }
#pragma unroll
            for (int nn = 0; nn < 8; nn++) {
                bfr[nn][0] = sB[ks + kq][wn + nn * 8 + r];
                bfr[nn][1] = sB[ks + kq + 4][wn + nn * 8 + r];
            }
#pragma unroll
            for (int mm = 0; mm < 2; mm++)
#pragma unroll
                for (int nn = 0; nn < 8; nn++)
                    mma8(acc[mm][nn], afr[mm], bfr[nn]);
        }
        __syncthreads();
    }

    float* out = &g_val[t][b][0][0];
#pragma unroll
    for (int mm = 0; mm < 2; mm++)
#pragma unroll
        for (int half = 0; half < 2; half++) {
            int row = m0 + wm + mm * 16 + r + half * 8;
            float bb = bias[row];
#pragma unroll
            for (int nn = 0; nn < 8; nn++) {
                int col = n0 + wn + nn * 8 + 2 * kq;
                float v0 = tf32r(acc[mm][nn][half * 2 + 0] + bb);
                float v1 = tf32r(acc[mm][nn][half * 2 + 1] + bb);
                *(float2*)&out[(size_t)row * HWD + col] = make_float2(v0, v1);
            }
        }
}

// ---------------------------------------------------------------------------
// K3: aff = fn^T fn (tf32 mma), symmetric: 36 of 64 128x128 block pairs.
// ---------------------------------------------------------------------------
__global__ void __launch_bounds__(256, 2)
k_aff_mma() {
    int t = blockIdx.z, b = blockIdx.y;
    int p = blockIdx.x;
    int bi = 0;
    while (p >= 8 - bi) { p -= 8 - bi; bi++; }
    int bj = bi + p;

    const float* fn = &g_fn[t][b][0][0];   // [C][HW], K-major
    __shared__ float sA[16][132];
    __shared__ float sB[16][132];

    int tid = threadIdx.x, lane = tid & 31, warp = tid >> 5;
    int wm = (warp >> 1) * 32, wn = (warp & 1) * 64;
    int r = lane >> 2, kq = lane & 3;
    int i0 = bi * 128, j0 = bj * 128;

    float acc[2][8][4];
#pragma unroll
    for (int mm = 0; mm < 2; mm++)
#pragma unroll
        for (int nn = 0; nn < 8; nn++)
#pragma unroll
            for (int i = 0; i < 4; i++) acc[mm][nn][i] = 0.f;

    int akk = tid >> 4, acol = (tid & 15) * 8;

    for (int c = 0; c < 16; c++) {
        int k0 = c * 16;
        const float* sa = &fn[(size_t)(k0 + akk) * HWD + i0 + acol];
        const float* sb = &fn[(size_t)(k0 + akk) * HWD + j0 + acol];
        *(float4*)&sA[akk][acol]     = *(const float4*)sa;
        *(float4*)&sA[akk][acol + 4] = *(const float4*)(sa + 4);
        *(float4*)&sB[akk][acol]     = *(const float4*)sb;
        *(float4*)&sB[akk][acol + 4] = *(const float4*)(sb + 4);
        __syncthreads();
#pragma unroll
        for (int ks = 0; ks < 16; ks += 8) {
            float afr[2][4], bfr[8][2];
#pragma unroll
            for (int mm = 0; mm < 2; mm++) {
                afr[mm][0] = sA[ks + kq][wm + mm * 16 + r];
                afr[mm][1] = sA[ks + kq][wm + mm * 16 + r + 8];
                afr[mm][2] = sA[ks + kq + 4][wm + mm * 16 + r];
                afr[mm][3] = sA[ks + kq + 4][wm + mm * 16 + r + 8];
            }
#pragma unroll
            for (int nn = 0; nn < 8; nn++) {
                bfr[nn][0] = sB[ks + kq][wn + nn * 8 + r];
                bfr[nn][1] = sB[ks + kq + 4][wn + nn * 8 + r];
            }
#pragma unroll
            for (int mm = 0; mm < 2; mm++)
#pragma unroll
                for (int nn = 0; nn < 8; nn++)
                    mma8(acc[mm][nn], afr[mm], bfr[nn]);
        }
        __syncthreads();
    }

    float* aff = &g_aff[t][b][0][0];
#pragma unroll
    for (int mm = 0; mm < 2; mm++)
#pragma unroll
        for (int half = 0; half < 2; half++) {
            int gi = i0 + wm + mm * 16 + r + half * 8;
#pragma unroll
            for (int nn = 0; nn < 8; nn++) {
                int gj = j0 + wn + nn * 8 + 2 * kq;
                float v0 = acc[mm][nn][half * 2 + 0];
                float v1 = acc[mm][nn][half * 2 + 1];
                *(float2*)&aff[(size_t)gi * HWD + gj] = make_float2(v0, v1);
                if (bi != bj) {
                    aff[(size_t)gj * HWD + gi]       = v0;
                    aff[(size_t)(gj + 1) * HWD + gi] = v1;
                }
            }
        }
}

// ---------------------------------------------------------------------------
// K4: grouped fusion conv (fp32), output tf32-rounded for the attend GEMM.
// ---------------------------------------------------------------------------
__global__ void k_fusion(const float* __restrict__ fw,
                         const float* __restrict__ fb) {
    int j = blockIdx.x, b = blockIdx.y;
    __shared__ float t0[34 * 34];
    __shared__ float t1[34 * 34];
    __shared__ float wsh[18];
    int tid = threadIdx.x;
    const float* a0 = &g_aff[0][b][j][0];
    const float* a1 = &g_aff[1][b][j][0];
    for (int idx = tid; idx < 34 * 34; idx += 256) {
        int y = idx / 34, x = idx - y * 34;
        int gy = y - 1, gx = x - 1;
        bool in = (unsigned)gy < 32u && (unsigned)gx < 32u;
        t0[idx] = in ? a0[gy * 32 + gx] : 0.f;
        t1[idx] = in ? a1[gy * 32 + gx] : 0.f;
    }
    if (tid < 18) wsh[tid] = fw[j * 18 + tid];
    __syncthreads();
    float bb = fb[j];
    float* out = &g_M[b][j][0];
#pragma unroll
    for (int q = 0; q < 4; q++) {
        int p = tid + 256 * q;
        int y = p >> 5, x = p & 31;
        float s = bb;
#pragma unroll
        for (int dy = 0; dy < 3; dy++)
#pragma unroll
            for (int dx = 0; dx < 3; dx++) {
                int ti = (y + dy) * 34 + (x + dx);
                s += t0[ti] * wsh[dy * 3 + dx];
                s += t1[ti] * wsh[9 + dy * 3 + dx];
            }
        out[p] = tf32r(s);
    }
}

// ---------------------------------------------------------------------------
// K5: attended[c][j] = sum_k val[c][k]*M[j][k]  (tf32 mma NT GEMM),
// fused epilogue out = 0.5*acc + 0.5*f straight to d_out.
// ---------------------------------------------------------------------------
__global__ void __launch_bounds__(256, 2)
k_attend_mma(const float* __restrict__ f0, const float* __restrict__ f1,
             float* __restrict__ out) {
    int t  = blockIdx.z;
    int b  = blockIdx.y;
    int bm = blockIdx.x & 1;
    int bn = blockIdx.x >> 1;
    const float* V  = &g_val[t][b][0][0];  // [256][1024], k contiguous
    const float* Mm = &g_M[b][0][0];       // [1024][1024], k contiguous

    __shared__ float sA[16][132];
    __shared__ float sB[16][132];

    int tid = threadIdx.x, lane = tid & 31, warp = tid >> 5;
    int wm = (warp >> 1) * 32, wn = (warp & 1) * 64;
    int r = lane >> 2, kq = lane & 3;
    int m0 = bm * 128, n0 = bn * 128;

    float acc[2][8][4];
#pragma unroll
    for (int mm = 0; mm < 2; mm++)
#pragma unroll
        for (int nn = 0; nn < 8; nn++)
#pragma unroll
            for (int i = 0; i < 4; i++) acc[mm][nn][i] = 0.f;

    int lrow = tid >> 1;          // 0..127
    int kh   = (tid & 1) * 8;     // 0 or 8

    for (int c = 0; c < 64; c++) {
        int k0 = c * 16;
        {
            const float* pa = &V[(size_t)(m0 + lrow) * HWD + k0 + kh];
            float4 v0 = *(const float4*)pa;
            float4 v1 = *(const float4*)(pa + 4);
            sA[kh + 0][lrow] = v0.x; sA[kh + 1][lrow] = v0.y;
            sA[kh + 2][lrow] = v0.z; sA[kh + 3][lrow] = v0.w;
            sA[kh + 4][lrow] = v1.x; sA[kh + 5][lrow] = v1.y;
            sA[kh + 6][lrow] = v1.z; sA[kh + 7][lrow] = v1.w;
            const float* pb = &Mm[(size_t)(n0 + lrow) * HWD + k0 + kh];
            float4 w0 = *(const float4*)pb;
            float4 w1 = *(const float4*)(pb + 4);
            sB[kh + 0][lrow] = w0.x; sB[kh + 1][lrow] = w0.y;
            sB[kh + 2][lrow] = w0.z; sB[kh + 3][lrow] = w0.w;
            sB[kh + 4][lrow] = w1.x; sB[kh + 5][lrow] = w1.y;
            sB[kh + 6][lrow] = w1.z; sB[kh + 7][lrow] = w1.w;
        }
        __syncthreads();
#pragma unroll
        for (int ks = 0; ks < 16; ks += 8) {
            float afr[2][4], bfr[8][2];
#pragma unroll
            for (int mm = 0; mm < 2; mm++) {
                afr[mm][0] = sA[ks + kq][wm + mm * 16 + r];
                afr[mm][1] = sA[ks + kq][wm + mm * 16 + r + 8];
                afr[mm][2] = sA[ks + kq + 4][wm + mm * 16 + r];
                afr[mm][3] = sA[ks + kq + 4][wm + mm * 16 + r + 8];
            }
#pragma unroll
            for (int nn = 0; nn < 8; nn++) {
                bfr[nn][0] = sB[ks + kq][wn + nn * 8 + r];
                bfr[nn][1] = sB[ks + kq + 4][wn + nn * 8 + r];
            }
#pragma unroll
            for (int mm = 0; mm < 2; mm++)
#pragma unroll
                for (int nn = 0; nn < 8; nn++)
                    mma8(acc[mm][nn], afr[mm], bfr[nn]);
        }
        __syncthreads();
    }

    const float* f = (t == 0 ? f0 : f1) + (size_t)b * CC * HWD;
    float* o = out + ((size_t)t * BB + b) * CC * HWD;
#pragma unroll
    for (int mm = 0; mm < 2; mm++)
#pragma unroll
        for (int half = 0; half < 2; half++) {
            int row = m0 + wm + mm * 16 + r + half * 8;
#pragma unroll
            for (int nn = 0; nn < 8; nn++) {
                int col = n0 + wn + nn * 8 + 2 * kq;
                float2 fv = *(const float2*)&f[(size_t)row * HWD + col];
                float v0 = 0.5f * acc[mm][nn][half * 2 + 0] + 0.5f * fv.x;
                float v1 = 0.5f * acc[mm][nn][half * 2 + 1] + 0.5f * fv.y;
                *(float2*)&o[(size_t)row * HWD + col] = make_float2(v0, v1);
            }
        }
}

// ---------------------------------------------------------------------------
extern "C" void kernel_launch(void* const* d_in, const int* in_sizes, int n_in,
                              void* d_out, int out_size) {
    const float* f0 = (const float*)d_in[0];   // features_seg
    const float* f1 = (const float*)d_in[1];   // features_depth
    const float* w0 = (const float*)d_in[2];   // proj_w_seg
    const float* b0 = (const float*)d_in[3];   // proj_b_seg
    const float* w1 = (const float*)d_in[4];   // proj_w_depth
    const float* b1 = (const float*)d_in[5];   // proj_b_depth
    const float* fw = (const float*)d_in[6];   // fusion_w
    const float* fb = (const float*)d_in[7];   // fusion_b
    float* out = (float*)d_out;

    k_normalize<<<dim3(4, 16, 2), 256>>>(f0, f1);
    k_wprep<<<dim3(256, 2), 256>>>(w0, w1);
    k_conv_mma<<<dim3(16, 16, 2), 256>>>(f0, f1, b0, b1);
    k_aff_mma<<<dim3(36, 16, 2), 256>>>();
    k_fusion<<<dim3(1024, 16), 256>>>(fw, fb);
    k_attend_mma<<<dim3(16, 16, 2), 256>>>(f0, f1, out);
}